// round 2
// baseline (speedup 1.0000x reference)
#include <cuda_runtime.h>
#include <math.h>
#include <stdint.h>

// ---------------- problem constants ----------------
#define DIN   32
#define H1    32
#define H2    64
#define DE    16
#define NATOM 50000
#define NEDGE 100000
#define NB    50
#define NPG   1000
#define MAMN  50        // amino acids per graph (M)
#define AAFD  95
#define GDIM  128
#define KST   3
#define TLAY  6
#define EAED  98        // amino edges
#define FAA   160       // padded h_aa width (159 used + 1 zero)
#define N1CAT 576       // 512 edge-W slices + 32 b_e1 slice + 32 root1
#define N2CAT 1152      // 1024 + 64 b_e2 + 64 root2
#define N3CAT 2688      // 384 init (K*G) + 2304 root (T*K*G)

// ---------------- device scratch ----------------
__device__ float g_C1[NATOM * N1CAT];          // 115 MB
__device__ float g_C2[(size_t)NATOM * N2CAT];  // 230 MB
__device__ float g_h1[NATOM * H1];
__device__ float g_h2[NATOM * H2];
__device__ float g_haa[NB * MAMN * FAA];
__device__ float g_C3[NB * MAMN * N3CAT];      // 26.9 MB
__device__ float g_ao[NB * KST * MAMN * GDIM]; // arma per-stack output
__device__ float g_W1cat[DIN * N1CAT];
__device__ float g_W2cat[H1 * N2CAT];
__device__ float g_W3cat[FAA * N3CAT];
__device__ int   g_off[MAMN + 1];
__device__ int   g_csrc[EAED];
__device__ float g_cnorm[EAED];

// ---------------- weight repack ----------------
__global__ void prep_weights(const float* __restrict__ We1, const float* __restrict__ be1,
                             const float* __restrict__ root1,
                             const float* __restrict__ We2, const float* __restrict__ be2,
                             const float* __restrict__ root2,
                             const float* __restrict__ ainit, const float* __restrict__ aroot) {
    int idx0 = blockIdx.x * blockDim.x + threadIdx.x;
    int stride = gridDim.x * blockDim.x;
    // W1cat[f][c]: c<512 -> We1[d,f*32+o]; c<544 -> be1 slice; else root1
    for (int idx = idx0; idx < DIN * N1CAT; idx += stride) {
        int f = idx / N1CAT, c = idx % N1CAT;
        float v;
        if (c < 512)      { int d = c >> 5, o = c & 31; v = We1[d * 1024 + f * 32 + o]; }
        else if (c < 544) { int o = c - 512;            v = be1[f * 32 + o]; }
        else              { int o = c - 544;            v = root1[f * 32 + o]; }
        g_W1cat[idx] = v;
    }
    for (int idx = idx0; idx < H1 * N2CAT; idx += stride) {
        int f = idx / N2CAT, c = idx % N2CAT;
        float v;
        if (c < 1024)      { int d = c >> 6, o = c & 63; v = We2[d * 2048 + f * 64 + o]; }
        else if (c < 1088) { int o = c - 1024;           v = be2[f * 64 + o]; }
        else               { int o = c - 1088;           v = root2[f * 64 + o]; }
        g_W2cat[idx] = v;
    }
    for (int idx = idx0; idx < FAA * N3CAT; idx += stride) {
        int f = idx / N3CAT, c = idx % N3CAT;
        float v = 0.f;
        if (f < 159) {
            if (c < 384) { int k = c >> 7, g = c & 127; v = ainit[(k * 159 + f) * 128 + g]; }
            else {
                int j = c - 384; int t = j / 384; int r = j - t * 384;
                int k = r >> 7, g = r & 127;
                v = aroot[((t * 3 + k) * 159 + f) * 128 + g];
            }
        }
        g_W3cat[idx] = v;
    }
}

// amino graph: degree norm + CSR by destination (serial, tiny)
__global__ void prep_csr(const int* __restrict__ aei) {
    if (blockIdx.x != 0 || threadIdx.x != 0) return;
    int deg[MAMN]; float dinv[MAMN]; int cur[MAMN];
    for (int m = 0; m < MAMN; m++) deg[m] = 0;
    for (int e = 0; e < EAED; e++) deg[aei[EAED + e]]++;
    for (int m = 0; m < MAMN; m++) dinv[m] = deg[m] > 0 ? 1.0f / sqrtf((float)deg[m]) : 0.0f;
    int off = 0;
    for (int m = 0; m < MAMN; m++) { g_off[m] = off; cur[m] = off; off += deg[m]; }
    g_off[MAMN] = off;
    for (int e = 0; e < EAED; e++) {
        int s = aei[e], d = aei[EAED + e];
        int slot = cur[d]++;
        g_csrc[slot] = s;
        g_cnorm[slot] = dinv[s] * dinv[d];
    }
}

// ---------------- generic fp32 tiled GEMM: C[M,N] = A[M,K] @ B[K,N] ----------------
// K % 16 == 0, N % 4 == 0. 256 threads, 64x64 tile, 4x4 microtile.
__global__ void gemm_kernel(const float* __restrict__ A, const float* __restrict__ B,
                            float* __restrict__ C, int M, int N, int K) {
    __shared__ float As[16][64];
    __shared__ float Bs[16][64];
    int bm = blockIdx.y * 64, bn = blockIdx.x * 64;
    int tid = threadIdx.x;
    int ty = tid >> 4, tx = tid & 15;
    float acc[4][4] = {};
    for (int k0 = 0; k0 < K; k0 += 16) {
        {
            int r = tid >> 2, c = (tid & 3) * 4;
            int gr = bm + r;
            float4 v = make_float4(0.f, 0.f, 0.f, 0.f);
            if (gr < M) v = *(const float4*)(A + (size_t)gr * K + k0 + c);
            As[c + 0][r] = v.x; As[c + 1][r] = v.y; As[c + 2][r] = v.z; As[c + 3][r] = v.w;
        }
        {
            int r = tid >> 4, c = (tid & 15) * 4;
            int gc = bn + c;
            float4 v = make_float4(0.f, 0.f, 0.f, 0.f);
            if (gc < N) v = *(const float4*)(B + (size_t)(k0 + r) * N + gc);
            *(float4*)&Bs[r][c] = v;
        }
        __syncthreads();
#pragma unroll
        for (int kk = 0; kk < 16; kk++) {
            float a[4], b[4];
            *(float4*)a = *(const float4*)&As[kk][ty * 4];
            *(float4*)b = *(const float4*)&Bs[kk][tx * 4];
#pragma unroll
            for (int i = 0; i < 4; i++)
#pragma unroll
                for (int j = 0; j < 4; j++) acc[i][j] += a[i] * b[j];
        }
        __syncthreads();
    }
#pragma unroll
    for (int i = 0; i < 4; i++) {
        int gr = bm + ty * 4 + i;
        if (gr < M && (bn + tx * 4) < N) {
            float4 v = make_float4(acc[i][0], acc[i][1], acc[i][2], acc[i][3]);
            *(float4*)(C + (size_t)gr * N + bn + tx * 4) = v;
        }
    }
}

// ---------------- conv init / relu ----------------
__global__ void init_h1_kernel(const float* __restrict__ bias1) {
    int idx = blockIdx.x * blockDim.x + threadIdx.x;
    int stride = gridDim.x * blockDim.x;
    for (int i = idx; i < NATOM * H1; i += stride) {
        int v = i >> 5, o = i & 31;
        g_h1[i] = g_C1[(size_t)v * N1CAT + 544 + o] + bias1[o];
    }
}
__global__ void init_h2_kernel(const float* __restrict__ bias2) {
    int idx = blockIdx.x * blockDim.x + threadIdx.x;
    int stride = gridDim.x * blockDim.x;
    for (int i = idx; i < NATOM * H2; i += stride) {
        int v = i >> 6, o = i & 63;
        g_h2[i] = g_C2[(size_t)v * N2CAT + 1088 + o] + bias2[o];
    }
}
__global__ void relu_kernel(float* __restrict__ p, int n) {
    int idx = blockIdx.x * blockDim.x + threadIdx.x;
    int stride = gridDim.x * blockDim.x;
    for (int i = idx; i < n; i += stride) p[i] = fmaxf(p[i], 0.f);
}

// ---------------- edge kernels (warp per edge) ----------------
__global__ void edge1_kernel(const int* __restrict__ ei, const float* __restrict__ ea) {
    int e = (blockIdx.x * blockDim.x + threadIdx.x) >> 5;
    int lane = threadIdx.x & 31;
    if (e >= NEDGE) return;
    int src = ei[e], dst = ei[NEDGE + e];
    float av = (lane < 16) ? ea[e * 16 + lane] : 0.f;
    const float* trow = g_C1 + (size_t)src * N1CAT;
    float acc = trow[512 + lane]; // b_e1 slice
#pragma unroll
    for (int d = 0; d < 16; d++) {
        float ed = __shfl_sync(0xffffffffu, av, d);
        acc += ed * trow[d * 32 + lane];
    }
    atomicAdd(g_h1 + (size_t)dst * H1 + lane, acc);
}
__global__ void edge2_kernel(const int* __restrict__ ei, const float* __restrict__ ea) {
    int e = (blockIdx.x * blockDim.x + threadIdx.x) >> 5;
    int lane = threadIdx.x & 31;
    if (e >= NEDGE) return;
    int src = ei[e], dst = ei[NEDGE + e];
    float av = (lane < 16) ? ea[e * 16 + lane] : 0.f;
    const float* trow = g_C2 + (size_t)src * N2CAT;
    float acc0 = trow[1024 + lane];
    float acc1 = trow[1056 + lane];
#pragma unroll
    for (int d = 0; d < 16; d++) {
        float ed = __shfl_sync(0xffffffffu, av, d);
        acc0 += ed * trow[d * 64 + lane];
        acc1 += ed * trow[d * 64 + 32 + lane];
    }
    atomicAdd(g_h2 + (size_t)dst * H2 + lane, acc0);
    atomicAdd(g_h2 + (size_t)dst * H2 + 32 + lane, acc1);
}

// ---------------- attention readout: atoms -> amino acids ----------------
__global__ void readout_kernel(const float* __restrict__ aaf, const int* __restrict__ labels,
                               const float* __restrict__ Wa, const float* __restrict__ ba) {
    __shared__ float lg[NPG];
    __shared__ float aas[MAMN * H2];
    __shared__ float red[256];
    __shared__ float was[H2];
    int b = blockIdx.x, tid = threadIdx.x;
    const float* Hrow = g_h2 + (size_t)b * NPG * H2;
    if (tid < H2) was[tid] = Wa[tid];
    __syncthreads();
    float lmax = -1e30f;
    for (int i = tid; i < NPG; i += 256) {
        float s = ba[0];
        const float* hr = Hrow + (size_t)i * H2;
        for (int o = 0; o < H2; o++) s += hr[o] * was[o];
        lg[i] = s;
        lmax = fmaxf(lmax, s);
    }
    red[tid] = lmax; __syncthreads();
    for (int s = 128; s > 0; s >>= 1) { if (tid < s) red[tid] = fmaxf(red[tid], red[tid + s]); __syncthreads(); }
    float mx = red[0]; __syncthreads();
    float lsum = 0.f;
    for (int i = tid; i < NPG; i += 256) { float e = expf(lg[i] - mx); lg[i] = e; lsum += e; }
    red[tid] = lsum; __syncthreads();
    for (int s = 128; s > 0; s >>= 1) { if (tid < s) red[tid] += red[tid + s]; __syncthreads(); }
    float inv = 1.f / red[0];
    for (int i = tid; i < MAMN * H2; i += 256) aas[i] = 0.f;
    __syncthreads();
    int warp = tid >> 5, lane = tid & 31;
    for (int i = warp; i < NPG; i += 8) {
        float w = lg[i] * inv;
        int m = labels[b * NPG + i];
        const float* hr = Hrow + (size_t)i * H2;
        atomicAdd(&aas[m * H2 + lane], w * hr[lane]);
        atomicAdd(&aas[m * H2 + 32 + lane], w * hr[32 + lane]);
    }
    __syncthreads();
    for (int idx = tid; idx < MAMN * FAA; idx += 256) {
        int m = idx / FAA, c = idx % FAA;
        float v;
        if (c < H2)       v = aas[m * H2 + c];
        else if (c < 159) v = aaf[((size_t)b * MAMN + m) * AAFD + (c - H2)];
        else              v = 0.f;
        g_haa[((size_t)b * MAMN + m) * FAA + c] = v;
    }
}

// ---------------- ARMA: one block per (graph, stack), all T layers fused ----------------
__global__ void arma_kernel(const float* __restrict__ arma_w, const float* __restrict__ arma_bias) {
    __shared__ float buf[MAMN * GDIM];  // 25.6 KB
    __shared__ float Ws[16 * GDIM];     // 8 KB
    __shared__ int   s_off[MAMN + 1];
    __shared__ int   s_src[EAED];
    __shared__ float s_norm[EAED];
    int b = blockIdx.x / KST, k = blockIdx.x % KST;
    int tid = threadIdx.x;              // 256
    int g = tid & 127, mh = tid >> 7;   // rows m = mh + 2r, r < 25
    if (tid < MAMN + 1) s_off[tid] = g_off[tid];
    if (tid < EAED) { s_src[tid] = g_csrc[tid]; s_norm[tid] = g_cnorm[tid]; }
    const float* Cb = g_C3 + (size_t)(b * MAMN) * N3CAT;
    for (int r = 0; r < 25; r++) {
        int m = mh + 2 * r;
        buf[m * GDIM + g] = Cb[(size_t)m * N3CAT + k * GDIM + g];
    }
    __syncthreads();
    for (int t = 0; t < TLAY; t++) {
        if (t > 0) {
            const float* Wg = arma_w + (size_t)((t - 1) * KST + k) * GDIM * GDIM;
            float acc[25];
#pragma unroll
            for (int r = 0; r < 25; r++) acc[r] = 0.f;
            for (int p0 = 0; p0 < GDIM; p0 += 16) {
                for (int j = tid; j < 16 * GDIM; j += 256) Ws[j] = Wg[(size_t)p0 * GDIM + j];
                __syncthreads();
#pragma unroll
                for (int pp = 0; pp < 16; pp++) {
                    float w = Ws[pp * GDIM + g];
#pragma unroll
                    for (int r = 0; r < 25; r++)
                        acc[r] += buf[(mh + 2 * r) * GDIM + (p0 + pp)] * w;
                }
                __syncthreads();
            }
            for (int r = 0; r < 25; r++) buf[(mh + 2 * r) * GDIM + g] = acc[r];
            __syncthreads();
        }
        // propagation + root + bias + relu
        float nv[25];
        float bias = arma_bias[(t * KST + k) * GDIM + g];
        for (int r = 0; r < 25; r++) {
            int m = mh + 2 * r;
            float s = 0.f;
            for (int j = s_off[m]; j < s_off[m + 1]; j++)
                s += s_norm[j] * buf[s_src[j] * GDIM + g];
            float v = s + Cb[(size_t)m * N3CAT + 384 + (t * KST + k) * GDIM + g] + bias;
            nv[r] = fmaxf(v, 0.f);
        }
        __syncthreads();
        for (int r = 0; r < 25; r++) buf[(mh + 2 * r) * GDIM + g] = nv[r];
        __syncthreads();
    }
    for (int r = 0; r < 25; r++) {
        int m = mh + 2 * r;
        g_ao[((size_t)(b * KST + k) * MAMN + m) * GDIM + g] = buf[m * GDIM + g];
    }
}

// ---------------- final: mean over stacks, attention over aminos, MLP head ----------------
__global__ void final_kernel(const float* __restrict__ Waa, const float* __restrict__ baa,
                             const float* __restrict__ W1, const float* __restrict__ b1,
                             const float* __restrict__ W2, const float* __restrict__ b2,
                             const float* __restrict__ W3, const float* __restrict__ b3,
                             const float* __restrict__ W4, const float* __restrict__ b4,
                             float* __restrict__ out) {
    __shared__ float gs[MAMN * 132];
    __shared__ float at[MAMN];
    __shared__ float ps[128], p1[64], p2[32], p3[16];
    int b = blockIdx.x, tid = threadIdx.x; // 128 threads
    const float* A = g_ao + (size_t)b * KST * MAMN * GDIM;
    for (int idx = tid; idx < MAMN * GDIM; idx += 128) {
        int m = idx >> 7, g = idx & 127;
        float v = (A[m * GDIM + g] + A[MAMN * GDIM + m * GDIM + g] +
                   A[2 * MAMN * GDIM + m * GDIM + g]) * (1.f / 3.f);
        gs[m * 132 + g] = v;
    }
    __syncthreads();
    if (tid < MAMN) {
        float s = baa[0];
        for (int g = 0; g < GDIM; g++) s += gs[tid * 132 + g] * Waa[g];
        at[tid] = s;
    }
    __syncthreads();
    if (tid == 0) {
        float mx = -1e30f;
        for (int m = 0; m < MAMN; m++) mx = fmaxf(mx, at[m]);
        float tot = 0.f;
        for (int m = 0; m < MAMN; m++) { float e = expf(at[m] - mx); at[m] = e; tot += e; }
        float inv = 1.f / tot;
        for (int m = 0; m < MAMN; m++) at[m] *= inv;
    }
    __syncthreads();
    { float s = 0.f; for (int m = 0; m < MAMN; m++) s += at[m] * gs[m * 132 + tid]; ps[tid] = s; }
    __syncthreads();
    if (tid < 64) { float s = b1[tid]; for (int i = 0; i < 128; i++) s += ps[i] * W1[i * 64 + tid]; p1[tid] = fmaxf(s, 0.f); }
    __syncthreads();
    if (tid < 32) { float s = b2[tid]; for (int i = 0; i < 64; i++) s += p1[i] * W2[i * 32 + tid]; p2[tid] = fmaxf(s, 0.f); }
    __syncthreads();
    if (tid < 16) { float s = b3[tid]; for (int i = 0; i < 32; i++) s += p2[i] * W3[i * 16 + tid]; p3[tid] = fmaxf(s, 0.f); }
    __syncthreads();
    if (tid == 0) { float s = b4[0]; for (int i = 0; i < 16; i++) s += p3[i] * W4[i]; out[b] = s; }
}

// ---------------- launch ----------------
extern "C" void kernel_launch(void* const* d_in, const int* in_sizes, int n_in,
                              void* d_out, int out_size) {
    const float* x         = (const float*)d_in[0];
    const float* edge_attr = (const float*)d_in[1];
    const float* aaf       = (const float*)d_in[2];
    const int*   ei        = (const int*)d_in[3];
    const int*   labels    = (const int*)d_in[4];
    const int*   aei       = (const int*)d_in[5];
    const float* We1   = (const float*)d_in[6];
    const float* be1   = (const float*)d_in[7];
    const float* root1 = (const float*)d_in[8];
    const float* bias1 = (const float*)d_in[9];
    const float* We2   = (const float*)d_in[10];
    const float* be2   = (const float*)d_in[11];
    const float* root2 = (const float*)d_in[12];
    const float* bias2 = (const float*)d_in[13];
    const float* WaAtom = (const float*)d_in[14];
    const float* baAtom = (const float*)d_in[15];
    const float* ainit  = (const float*)d_in[16];
    const float* armaw  = (const float*)d_in[17];
    const float* aroot  = (const float*)d_in[18];
    const float* abias  = (const float*)d_in[19];
    const float* Waa    = (const float*)d_in[20];
    const float* baa    = (const float*)d_in[21];
    const float* W1 = (const float*)d_in[22];
    const float* b1 = (const float*)d_in[23];
    const float* W2 = (const float*)d_in[24];
    const float* b2 = (const float*)d_in[25];
    const float* W3 = (const float*)d_in[26];
    const float* b3 = (const float*)d_in[27];
    const float* W4 = (const float*)d_in[28];
    const float* b4 = (const float*)d_in[29];
    float* out = (float*)d_out;

    void *pC1, *pC2, *pC3, *ph1, *ph2, *phaa, *pW1c, *pW2c, *pW3c;
    cudaGetSymbolAddress(&pC1, g_C1);
    cudaGetSymbolAddress(&pC2, g_C2);
    cudaGetSymbolAddress(&pC3, g_C3);
    cudaGetSymbolAddress(&ph1, g_h1);
    cudaGetSymbolAddress(&ph2, g_h2);
    cudaGetSymbolAddress(&phaa, g_haa);
    cudaGetSymbolAddress(&pW1c, g_W1cat);
    cudaGetSymbolAddress(&pW2c, g_W2cat);
    cudaGetSymbolAddress(&pW3c, g_W3cat);

    prep_weights<<<256, 256>>>(We1, be1, root1, We2, be2, root2, ainit, aroot);
    prep_csr<<<1, 32>>>(aei);

    // conv1
    {
        dim3 grid(N1CAT / 64, (NATOM + 63) / 64);
        gemm_kernel<<<grid, 256>>>(x, (const float*)pW1c, (float*)pC1, NATOM, N1CAT, DIN);
    }
    init_h1_kernel<<<2048, 256>>>(bias1);
    edge1_kernel<<<NEDGE / 8, 256>>>(ei, edge_attr);
    relu_kernel<<<2048, 256>>>((float*)ph1, NATOM * H1);

    // conv2
    {
        dim3 grid(N2CAT / 64, (NATOM + 63) / 64);
        gemm_kernel<<<grid, 256>>>((const float*)ph1, (const float*)pW2c, (float*)pC2, NATOM, N2CAT, H1);
    }
    init_h2_kernel<<<2048, 256>>>(bias2);
    edge2_kernel<<<NEDGE / 8, 256>>>(ei, edge_attr);
    relu_kernel<<<2048, 256>>>((float*)ph2, NATOM * H2);

    // atom -> amino readout
    readout_kernel<<<NB, 256>>>(aaf, labels, WaAtom, baAtom);

    // ARMA init + root precompute GEMM: [2500,160] @ [160,2688]
    {
        dim3 grid(N3CAT / 64, (NB * MAMN + 63) / 64);
        gemm_kernel<<<grid, 256>>>((const float*)phaa, (const float*)pW3c, (float*)pC3,
                                   NB * MAMN, N3CAT, FAA);
    }

    // ARMA recurrence (150 independent blocks, all T layers fused)
    arma_kernel<<<NB * KST, 256>>>(armaw, abias);

    // head
    final_kernel<<<NB, 128>>>(Waa, baa, W1, b1, W2, b2, W3, b3, W4, b4, out);
}

// round 3
// speedup vs baseline: 1.0266x; 1.0266x over previous
#include <cuda_runtime.h>
#include <math.h>
#include <stdint.h>

// ---------------- problem constants ----------------
#define DIN   32
#define H1    32
#define H2    64
#define DE    16
#define NATOM 50000
#define NEDGE 100000
#define NB    50
#define NPG   1000
#define MAMN  50
#define AAFD  95
#define GDIM  128
#define KST   3
#define TLAY  6
#define EAED  98
#define FAA   160
#define N1CAT 576       // 512 edge-W + 32 b_e1 + 32 root1
#define N2CAT 1152      // 1024 edge-W + 64 b_e2 + 64 root2
#define N3CAT 2688      // 384 init (K*G) + 2304 root (T*K*G)

// ---------------- device scratch ----------------
__device__ float g_C1[NATOM * N1CAT];
__device__ float g_C2[(size_t)NATOM * N2CAT];
__device__ float g_h1[NATOM * H1];
__device__ float g_h2[NATOM * H2];
__device__ float g_haa[NB * MAMN * FAA];
__device__ float g_C3[NB * MAMN * N3CAT];
__device__ float g_ao[NB * KST * MAMN * GDIM];
__device__ float g_W1cat[DIN * N1CAT];
__device__ float g_W2cat[H1 * N2CAT];
__device__ float g_W3cat[FAA * N3CAT];
__device__ int   g_off[MAMN + 1];
__device__ int   g_csrc[EAED];
__device__ float g_cnorm[EAED];

// ---------------- f32x2 helpers ----------------
__device__ __forceinline__ unsigned long long pk2(float x) {
    unsigned long long r; unsigned u = __float_as_uint(x);
    asm("mov.b64 %0, {%1, %1};" : "=l"(r) : "r"(u));
    return r;
}
__device__ __forceinline__ float2 unpk2(unsigned long long v) {
    unsigned lo, hi;
    asm("mov.b64 {%0, %1}, %2;" : "=r"(lo), "=r"(hi) : "l"(v));
    return make_float2(__uint_as_float(lo), __uint_as_float(hi));
}
#define FMA2(acc, a, b) \
    asm("fma.rn.f32x2 %0, %1, %2, %3;" : "=l"(acc) : "l"(a), "l"(b), "l"(acc))

// ---------------- weight repack ----------------
__global__ void prep_weights(const float* __restrict__ We1, const float* __restrict__ be1,
                             const float* __restrict__ root1,
                             const float* __restrict__ We2, const float* __restrict__ be2,
                             const float* __restrict__ root2,
                             const float* __restrict__ ainit, const float* __restrict__ aroot) {
    int idx0 = blockIdx.x * blockDim.x + threadIdx.x;
    int stride = gridDim.x * blockDim.x;
    for (int idx = idx0; idx < DIN * N1CAT; idx += stride) {
        int f = idx / N1CAT, c = idx % N1CAT;
        float v;
        if (c < 512)      { int d = c >> 5, o = c & 31; v = We1[d * 1024 + f * 32 + o]; }
        else if (c < 544) { int o = c - 512;            v = be1[f * 32 + o]; }
        else              { int o = c - 544;            v = root1[f * 32 + o]; }
        g_W1cat[idx] = v;
    }
    for (int idx = idx0; idx < H1 * N2CAT; idx += stride) {
        int f = idx / N2CAT, c = idx % N2CAT;
        float v;
        if (c < 1024)      { int d = c >> 6, o = c & 63; v = We2[d * 2048 + f * 64 + o]; }
        else if (c < 1088) { int o = c - 1024;           v = be2[f * 64 + o]; }
        else               { int o = c - 1088;           v = root2[f * 64 + o]; }
        g_W2cat[idx] = v;
    }
    for (int idx = idx0; idx < FAA * N3CAT; idx += stride) {
        int f = idx / N3CAT, c = idx % N3CAT;
        float v = 0.f;
        if (f < 159) {
            if (c < 384) { int k = c >> 7, g = c & 127; v = ainit[(k * 159 + f) * 128 + g]; }
            else {
                int j = c - 384; int t = j / 384; int r = j - t * 384;
                int k = r >> 7, g = r & 127;
                v = aroot[((t * 3 + k) * 159 + f) * 128 + g];
            }
        }
        g_W3cat[idx] = v;
    }
}

__global__ void prep_csr(const int* __restrict__ aei) {
    if (blockIdx.x != 0 || threadIdx.x != 0) return;
    int deg[MAMN]; float dinv[MAMN]; int cur[MAMN];
    for (int m = 0; m < MAMN; m++) deg[m] = 0;
    for (int e = 0; e < EAED; e++) deg[aei[EAED + e]]++;
    for (int m = 0; m < MAMN; m++) dinv[m] = deg[m] > 0 ? 1.0f / sqrtf((float)deg[m]) : 0.0f;
    int off = 0;
    for (int m = 0; m < MAMN; m++) { g_off[m] = off; cur[m] = off; off += deg[m]; }
    g_off[MAMN] = off;
    for (int e = 0; e < EAED; e++) {
        int s = aei[e], d = aei[EAED + e];
        int slot = cur[d]++;
        g_csrc[slot] = s;
        g_cnorm[slot] = dinv[s] * dinv[d];
    }
}

// ---------------- f32x2 GEMM: C[M,N] = A[M,K] @ B[K,N] ----------------
// 128x128 tile, 256 threads, 8x8 microtile via fma.rn.f32x2.
// CONV mode: cols < rootStart -> C; cols in [rootStart, N) -> hbuf (+bias).
// All region boundaries (rootStart, N) are multiples of 16 in conv mode.
template <bool RELU_A, bool CONV>
__global__ __launch_bounds__(256, 2)
void gemm_x2_kernel(const float* __restrict__ A, const float* __restrict__ B,
                    float* __restrict__ C, int M, int N, int K,
                    int rootStart, float* __restrict__ hbuf, int HW,
                    const float* __restrict__ bias) {
    __shared__ float As[32][128];
    __shared__ float Bs[32][128];
    int bm = blockIdx.y * 128, bn = blockIdx.x * 128;
    int tid = threadIdx.x;
    int ty = tid >> 4, tx = tid & 15;
    unsigned long long acc[8][4];
#pragma unroll
    for (int i = 0; i < 8; i++)
#pragma unroll
        for (int j = 0; j < 4; j++) acc[i][j] = 0ull;

    for (int k0 = 0; k0 < K; k0 += 32) {
        // load A tile (transposed into As[k][r]); 4 float4 per thread
#pragma unroll
        for (int j = 0; j < 4; j++) {
            int f4 = tid + j * 256;
            int r = f4 >> 3, cq = (f4 & 7) * 4;
            int gr = bm + r;
            float4 v = make_float4(0.f, 0.f, 0.f, 0.f);
            if (gr < M) {
                v = *(const float4*)(A + (size_t)gr * K + k0 + cq);
                if (RELU_A) {
                    v.x = fmaxf(v.x, 0.f); v.y = fmaxf(v.y, 0.f);
                    v.z = fmaxf(v.z, 0.f); v.w = fmaxf(v.w, 0.f);
                }
            }
            As[cq + 0][r] = v.x; As[cq + 1][r] = v.y;
            As[cq + 2][r] = v.z; As[cq + 3][r] = v.w;
        }
        // load B tile; 4 float4 per thread
#pragma unroll
        for (int j = 0; j < 4; j++) {
            int f4 = tid + j * 256;
            int r = f4 >> 5, c4 = (f4 & 31) * 4;
            int gc = bn + c4;
            float4 v = make_float4(0.f, 0.f, 0.f, 0.f);
            if (gc < N) v = *(const float4*)(B + (size_t)(k0 + r) * N + gc);
            *(float4*)&Bs[r][c4] = v;
        }
        __syncthreads();
#pragma unroll
        for (int kk = 0; kk < 32; kk++) {
            float4 av0 = *(const float4*)&As[kk][ty * 8];
            float4 av1 = *(const float4*)&As[kk][ty * 8 + 4];
            ulonglong2 bv0 = *(const ulonglong2*)&Bs[kk][tx * 8];
            ulonglong2 bv1 = *(const ulonglong2*)&Bs[kk][tx * 8 + 4];
            unsigned long long a2[8];
            a2[0] = pk2(av0.x); a2[1] = pk2(av0.y); a2[2] = pk2(av0.z); a2[3] = pk2(av0.w);
            a2[4] = pk2(av1.x); a2[5] = pk2(av1.y); a2[6] = pk2(av1.z); a2[7] = pk2(av1.w);
            unsigned long long bb[4] = {bv0.x, bv0.y, bv1.x, bv1.y};
#pragma unroll
            for (int i = 0; i < 8; i++) {
                FMA2(acc[i][0], a2[i], bb[0]);
                FMA2(acc[i][1], a2[i], bb[1]);
                FMA2(acc[i][2], a2[i], bb[2]);
                FMA2(acc[i][3], a2[i], bb[3]);
            }
        }
        __syncthreads();
    }
    // epilogue
#pragma unroll
    for (int i = 0; i < 8; i++) {
        int gr = bm + ty * 8 + i;
        if (gr >= M) continue;
#pragma unroll
        for (int h = 0; h < 2; h++) {
            int c0 = bn + tx * 8 + h * 4;
            float2 p0 = unpk2(acc[i][2 * h]);
            float2 p1 = unpk2(acc[i][2 * h + 1]);
            float4 v = make_float4(p0.x, p0.y, p1.x, p1.y);
            if (CONV) {
                if (c0 < rootStart) {
                    *(float4*)(C + (size_t)gr * N + c0) = v;
                } else if (c0 < N) {
                    int idx = c0 - rootStart;
                    v.x += bias[idx]; v.y += bias[idx + 1];
                    v.z += bias[idx + 2]; v.w += bias[idx + 3];
                    *(float4*)(hbuf + (size_t)gr * HW + idx) = v;
                }
            } else {
                if (c0 < N) *(float4*)(C + (size_t)gr * N + c0) = v;
            }
        }
    }
}

// ---------------- edge kernels (warp per edge) ----------------
__global__ void edge1_kernel(const int* __restrict__ ei, const float* __restrict__ ea) {
    int e = (blockIdx.x * blockDim.x + threadIdx.x) >> 5;
    int lane = threadIdx.x & 31;
    if (e >= NEDGE) return;
    int src = ei[e], dst = ei[NEDGE + e];
    float av = (lane < 16) ? ea[e * 16 + lane] : 0.f;
    const float* trow = g_C1 + (size_t)src * N1CAT;
    float acc = trow[512 + lane];
#pragma unroll
    for (int d = 0; d < 16; d++) {
        float ed = __shfl_sync(0xffffffffu, av, d);
        acc += ed * trow[d * 32 + lane];
    }
    atomicAdd(g_h1 + (size_t)dst * H1 + lane, acc);
}
__global__ void edge2_kernel(const int* __restrict__ ei, const float* __restrict__ ea) {
    int e = (blockIdx.x * blockDim.x + threadIdx.x) >> 5;
    int lane = threadIdx.x & 31;
    if (e >= NEDGE) return;
    int src = ei[e], dst = ei[NEDGE + e];
    float av = (lane < 16) ? ea[e * 16 + lane] : 0.f;
    const float* trow = g_C2 + (size_t)src * N2CAT;
    float acc0 = trow[1024 + lane];
    float acc1 = trow[1056 + lane];
#pragma unroll
    for (int d = 0; d < 16; d++) {
        float ed = __shfl_sync(0xffffffffu, av, d);
        acc0 += ed * trow[d * 64 + lane];
        acc1 += ed * trow[d * 64 + 32 + lane];
    }
    atomicAdd(g_h2 + (size_t)dst * H2 + lane, acc0);
    atomicAdd(g_h2 + (size_t)dst * H2 + 32 + lane, acc1);
}

// ---------------- attention readout (relu(h2) fused in) ----------------
__global__ void readout_kernel(const float* __restrict__ aaf, const int* __restrict__ labels,
                               const float* __restrict__ Wa, const float* __restrict__ ba) {
    __shared__ float lg[NPG];
    __shared__ float aas[MAMN * H2];
    __shared__ float red[256];
    __shared__ float was[H2];
    int b = blockIdx.x, tid = threadIdx.x;
    const float* Hrow = g_h2 + (size_t)b * NPG * H2;
    if (tid < H2) was[tid] = Wa[tid];
    __syncthreads();
    float lmax = -1e30f;
    for (int i = tid; i < NPG; i += 256) {
        float s = ba[0];
        const float* hr = Hrow + (size_t)i * H2;
        for (int o = 0; o < H2; o++) s += fmaxf(hr[o], 0.f) * was[o];
        lg[i] = s;
        lmax = fmaxf(lmax, s);
    }
    red[tid] = lmax; __syncthreads();
    for (int s = 128; s > 0; s >>= 1) { if (tid < s) red[tid] = fmaxf(red[tid], red[tid + s]); __syncthreads(); }
    float mx = red[0]; __syncthreads();
    float lsum = 0.f;
    for (int i = tid; i < NPG; i += 256) { float e = expf(lg[i] - mx); lg[i] = e; lsum += e; }
    red[tid] = lsum; __syncthreads();
    for (int s = 128; s > 0; s >>= 1) { if (tid < s) red[tid] += red[tid + s]; __syncthreads(); }
    float inv = 1.f / red[0];
    for (int i = tid; i < MAMN * H2; i += 256) aas[i] = 0.f;
    __syncthreads();
    int warp = tid >> 5, lane = tid & 31;
    for (int i = warp; i < NPG; i += 8) {
        float w = lg[i] * inv;
        int m = labels[b * NPG + i];
        const float* hr = Hrow + (size_t)i * H2;
        atomicAdd(&aas[m * H2 + lane], w * fmaxf(hr[lane], 0.f));
        atomicAdd(&aas[m * H2 + 32 + lane], w * fmaxf(hr[32 + lane], 0.f));
    }
    __syncthreads();
    for (int idx = tid; idx < MAMN * FAA; idx += 256) {
        int m = idx / FAA, c = idx % FAA;
        float v;
        if (c < H2)       v = aas[m * H2 + c];
        else if (c < 159) v = aaf[((size_t)b * MAMN + m) * AAFD + (c - H2)];
        else              v = 0.f;
        g_haa[((size_t)b * MAMN + m) * FAA + c] = v;
    }
}

// ---------------- ARMA: one block per (graph, stack); 512 threads ----------------
__global__ __launch_bounds__(512)
void arma_kernel(const float* __restrict__ arma_w, const float* __restrict__ arma_bias) {
    __shared__ float buf[MAMN * GDIM];
    __shared__ float Ws[16 * GDIM];
    __shared__ int   s_off[MAMN + 1];
    __shared__ int   s_src[EAED];
    __shared__ float s_norm[EAED];
    int b = blockIdx.x / KST, k = blockIdx.x % KST;
    int tid = threadIdx.x;
    int g = tid & 127, mh = tid >> 7;  // 0..3; rows m = mh + 4r, r < 13
    if (tid < MAMN + 1) s_off[tid] = g_off[tid];
    if (tid < EAED) { s_src[tid] = g_csrc[tid]; s_norm[tid] = g_cnorm[tid]; }
    const float* Cb = g_C3 + (size_t)(b * MAMN) * N3CAT;
#pragma unroll
    for (int r = 0; r < 13; r++) {
        int m = mh + 4 * r;
        if (m < MAMN) buf[m * GDIM + g] = Cb[(size_t)m * N3CAT + k * GDIM + g];
    }
    __syncthreads();
    for (int t = 0; t < TLAY; t++) {
        if (t > 0) {
            const float* Wg = arma_w + (size_t)((t - 1) * KST + k) * GDIM * GDIM;
            float acc[13];
#pragma unroll
            for (int r = 0; r < 13; r++) acc[r] = 0.f;
            for (int p0 = 0; p0 < GDIM; p0 += 16) {
                for (int j = tid; j < 16 * GDIM; j += 512) Ws[j] = Wg[(size_t)p0 * GDIM + j];
                __syncthreads();
#pragma unroll
                for (int pp = 0; pp < 16; pp++) {
                    float w = Ws[pp * GDIM + g];
#pragma unroll
                    for (int r = 0; r < 13; r++) {
                        int m = mh + 4 * r;
                        if (m < MAMN) acc[r] += buf[m * GDIM + (p0 + pp)] * w;
                    }
                }
                __syncthreads();
            }
#pragma unroll
            for (int r = 0; r < 13; r++) {
                int m = mh + 4 * r;
                if (m < MAMN) buf[m * GDIM + g] = acc[r];
            }
            __syncthreads();
        }
        float nv[13];
        float bias = arma_bias[(t * KST + k) * GDIM + g];
#pragma unroll
        for (int r = 0; r < 13; r++) {
            int m = mh + 4 * r;
            if (m < MAMN) {
                float s = 0.f;
                for (int j = s_off[m]; j < s_off[m + 1]; j++)
                    s += s_norm[j] * buf[s_src[j] * GDIM + g];
                float v = s + Cb[(size_t)m * N3CAT + 384 + (t * KST + k) * GDIM + g] + bias;
                nv[r] = fmaxf(v, 0.f);
            }
        }
        __syncthreads();
#pragma unroll
        for (int r = 0; r < 13; r++) {
            int m = mh + 4 * r;
            if (m < MAMN) buf[m * GDIM + g] = nv[r];
        }
        __syncthreads();
    }
#pragma unroll
    for (int r = 0; r < 13; r++) {
        int m = mh + 4 * r;
        if (m < MAMN)
            g_ao[((size_t)(b * KST + k) * MAMN + m) * GDIM + g] = buf[m * GDIM + g];
    }
}

// ---------------- final head ----------------
__global__ void final_kernel(const float* __restrict__ Waa, const float* __restrict__ baa,
                             const float* __restrict__ W1, const float* __restrict__ b1,
                             const float* __restrict__ W2, const float* __restrict__ b2,
                             const float* __restrict__ W3, const float* __restrict__ b3,
                             const float* __restrict__ W4, const float* __restrict__ b4,
                             float* __restrict__ out) {
    __shared__ float gs[MAMN * 132];
    __shared__ float at[MAMN];
    __shared__ float ps[128], p1[64], p2[32], p3[16];
    int b = blockIdx.x, tid = threadIdx.x; // 128 threads
    const float* A = g_ao + (size_t)b * KST * MAMN * GDIM;
    for (int idx = tid; idx < MAMN * GDIM; idx += 128) {
        int m = idx >> 7, g = idx & 127;
        float v = (A[m * GDIM + g] + A[MAMN * GDIM + m * GDIM + g] +
                   A[2 * MAMN * GDIM + m * GDIM + g]) * (1.f / 3.f);
        gs[m * 132 + g] = v;
    }
    __syncthreads();
    if (tid < MAMN) {
        float s = baa[0];
        for (int g = 0; g < GDIM; g++) s += gs[tid * 132 + g] * Waa[g];
        at[tid] = s;
    }
    __syncthreads();
    if (tid == 0) {
        float mx = -1e30f;
        for (int m = 0; m < MAMN; m++) mx = fmaxf(mx, at[m]);
        float tot = 0.f;
        for (int m = 0; m < MAMN; m++) { float e = expf(at[m] - mx); at[m] = e; tot += e; }
        float inv = 1.f / tot;
        for (int m = 0; m < MAMN; m++) at[m] *= inv;
    }
    __syncthreads();
    { float s = 0.f; for (int m = 0; m < MAMN; m++) s += at[m] * gs[m * 132 + tid]; ps[tid] = s; }
    __syncthreads();
    if (tid < 64) { float s = b1[tid]; for (int i = 0; i < 128; i++) s += ps[i] * W1[i * 64 + tid]; p1[tid] = fmaxf(s, 0.f); }
    __syncthreads();
    if (tid < 32) { float s = b2[tid]; for (int i = 0; i < 64; i++) s += p1[i] * W2[i * 32 + tid]; p2[tid] = fmaxf(s, 0.f); }
    __syncthreads();
    if (tid < 16) { float s = b3[tid]; for (int i = 0; i < 32; i++) s += p2[i] * W3[i * 16 + tid]; p3[tid] = fmaxf(s, 0.f); }
    __syncthreads();
    if (tid == 0) { float s = b4[0]; for (int i = 0; i < 16; i++) s += p3[i] * W4[i]; out[b] = s; }
}

// ---------------- launch ----------------
extern "C" void kernel_launch(void* const* d_in, const int* in_sizes, int n_in,
                              void* d_out, int out_size) {
    const float* x         = (const float*)d_in[0];
    const float* edge_attr = (const float*)d_in[1];
    const float* aaf       = (const float*)d_in[2];
    const int*   ei        = (const int*)d_in[3];
    const int*   labels    = (const int*)d_in[4];
    const int*   aei       = (const int*)d_in[5];
    const float* We1   = (const float*)d_in[6];
    const float* be1   = (const float*)d_in[7];
    const float* root1 = (const float*)d_in[8];
    const float* bias1 = (const float*)d_in[9];
    const float* We2   = (const float*)d_in[10];
    const float* be2   = (const float*)d_in[11];
    const float* root2 = (const float*)d_in[12];
    const float* bias2 = (const float*)d_in[13];
    const float* WaAtom = (const float*)d_in[14];
    const float* baAtom = (const float*)d_in[15];
    const float* armaw  = (const float*)d_in[17];
    const float* abias  = (const float*)d_in[19];
    const float* Waa    = (const float*)d_in[20];
    const float* baa    = (const float*)d_in[21];
    const float* W1 = (const float*)d_in[22];
    const float* b1 = (const float*)d_in[23];
    const float* W2 = (const float*)d_in[24];
    const float* b2 = (const float*)d_in[25];
    const float* W3 = (const float*)d_in[26];
    const float* b3 = (const float*)d_in[27];
    const float* W4 = (const float*)d_in[28];
    const float* b4 = (const float*)d_in[29];
    float* out = (float*)d_out;

    void *pC1, *pC2, *pC3, *ph1, *ph2, *phaa, *pW1c, *pW2c, *pW3c;
    cudaGetSymbolAddress(&pC1, g_C1);
    cudaGetSymbolAddress(&pC2, g_C2);
    cudaGetSymbolAddress(&pC3, g_C3);
    cudaGetSymbolAddress(&ph1, g_h1);
    cudaGetSymbolAddress(&ph2, g_h2);
    cudaGetSymbolAddress(&phaa, g_haa);
    cudaGetSymbolAddress(&pW1c, g_W1cat);
    cudaGetSymbolAddress(&pW2c, g_W2cat);
    cudaGetSymbolAddress(&pW3c, g_W3cat);

    prep_weights<<<256, 256>>>(We1, be1, root1, We2, be2, root2,
                               (const float*)d_in[16], (const float*)d_in[18]);

    // conv1: C1 + h1 base (root+bias fused into epilogue)
    {
        dim3 grid((N1CAT + 127) / 128, (NATOM + 127) / 128);
        gemm_x2_kernel<false, true><<<grid, 256>>>(
            x, (const float*)pW1c, (float*)pC1, NATOM, N1CAT, DIN,
            544, (float*)ph1, H1, bias1);
    }
    edge1_kernel<<<NEDGE / 8, 256>>>(ei, edge_attr);

    // conv2: A = relu(h1) fused into load
    {
        dim3 grid((N2CAT + 127) / 128, (NATOM + 127) / 128);
        gemm_x2_kernel<true, true><<<grid, 256>>>(
            (const float*)ph1, (const float*)pW2c, (float*)pC2, NATOM, N2CAT, H1,
            1088, (float*)ph2, H2, bias2);
    }
    edge2_kernel<<<NEDGE / 8, 256>>>(ei, edge_attr);

    // atom -> amino readout (relu(h2) fused into reads)
    readout_kernel<<<NB, 256>>>(aaf, labels, WaAtom, baAtom);

    prep_csr<<<1, 32>>>(aei);

    // ARMA init + root precompute GEMM: [2500,160] @ [160,2688]
    {
        dim3 grid((N3CAT + 127) / 128, (NB * MAMN + 127) / 128);
        gemm_x2_kernel<false, false><<<grid, 256>>>(
            (const float*)phaa, (const float*)pW3c, (float*)pC3,
            NB * MAMN, N3CAT, FAA, N3CAT, nullptr, 0, nullptr);
    }

    arma_kernel<<<NB * KST, 512>>>(armaw, abias);

    final_kernel<<<NB, 128>>>(Waa, baa, W1, b1, W2, b2, W3, b3, W4, b4, out);
}